// round 17
// baseline (speedup 1.0000x reference)
#include <cuda_runtime.h>
#include <cuda_bf16.h>
#include <math.h>
#include <stdint.h>

// ---------------- Problem constants ----------------
#define N_TOK 16384
#define D_IN  1024
#define D_OUT 1024
#define N_EXP 8
#define RANK  16
#define SCALING 2.0f   // ALPHA / R

// ---------------- Device scratch ----------------
__device__ __nv_bfloat16 g_Ah[(size_t)N_TOK * D_IN];   // tokens hi   [n][k]
__device__ __nv_bfloat16 g_Al[(size_t)N_TOK * D_IN];   // tokens lo
__device__ __nv_bfloat16 g_Wh[(size_t)D_IN * D_OUT];   // W_base hi   [k][n]
__device__ __nv_bfloat16 g_Wl[(size_t)D_IN * D_OUT];
__device__ __nv_bfloat16 g_Bc_h[D_IN * 160];           // [A_flat|Wg|0] hi [k][j]
__device__ __nv_bfloat16 g_Bc_l[D_IN * 160];
__device__ __nv_bfloat16 g_Bf_h[128 * D_OUT];          // B_flat hi   [j][m]
__device__ __nv_bfloat16 g_Bf_l[128 * D_OUT];
__device__ __nv_bfloat16 g_Hh[(size_t)N_TOK * 128];    // gated H hi  [n][j]
__device__ __nv_bfloat16 g_Hl[(size_t)N_TOK * 128];

// ---------------- PTX helpers ----------------
__device__ __forceinline__ uint32_t s2u(const void* p) {
    uint32_t a;
    asm("{ .reg .u64 t; cvta.to.shared.u64 t, %1; cvt.u32.u64 %0, t; }"
        : "=r"(a) : "l"(p));
    return a;
}
__device__ __forceinline__ void cp16(uint32_t dst, const void* src) {
    asm volatile("cp.async.cg.shared.global [%0], [%1], 16;"
                 :: "r"(dst), "l"(__cvta_generic_to_global(src)));
}
#define CP_COMMIT() asm volatile("cp.async.commit_group;" ::: "memory")

__device__ __forceinline__ void ldsm4(uint32_t* r, uint32_t a) {
    asm volatile("ldmatrix.sync.aligned.m8n8.x4.shared.b16 {%0,%1,%2,%3}, [%4];"
                 : "=r"(r[0]), "=r"(r[1]), "=r"(r[2]), "=r"(r[3]) : "r"(a));
}
__device__ __forceinline__ void ldsm4t(uint32_t* r, uint32_t a) {
    asm volatile("ldmatrix.sync.aligned.m8n8.x4.trans.shared.b16 {%0,%1,%2,%3}, [%4];"
                 : "=r"(r[0]), "=r"(r[1]), "=r"(r[2]), "=r"(r[3]) : "r"(a));
}
__device__ __forceinline__ void mma_bf16(float* c, const uint32_t* a,
                                         uint32_t b0, uint32_t b1) {
    asm volatile(
        "mma.sync.aligned.m16n8k16.row.col.f32.bf16.bf16.f32 "
        "{%0,%1,%2,%3}, {%4,%5,%6,%7}, {%8,%9}, {%0,%1,%2,%3};"
        : "+f"(c[0]), "+f"(c[1]), "+f"(c[2]), "+f"(c[3])
        : "r"(a[0]), "r"(a[1]), "r"(a[2]), "r"(a[3]), "r"(b0), "r"(b1));
}

// ---------------- Conversion helpers ----------------
__device__ __forceinline__ void split2(float v, __nv_bfloat16& h, __nv_bfloat16& l) {
    h = __float2bfloat16(v);
    l = __float2bfloat16(v - __bfloat162float(h));
}
__device__ __forceinline__ uint32_t pack2(__nv_bfloat16 a, __nv_bfloat16 b) {
    return (uint32_t)__bfloat16_as_ushort(a) | ((uint32_t)__bfloat16_as_ushort(b) << 16);
}
__device__ __forceinline__ void split_store4(const float4& v, uint2* ph, uint2* pl) {
    __nv_bfloat16 h0, h1, h2, h3, l0, l1, l2, l3;
    split2(v.x, h0, l0); split2(v.y, h1, l1);
    split2(v.z, h2, l2); split2(v.w, h3, l3);
    *ph = make_uint2(pack2(h0, h1), pack2(h2, h3));
    *pl = make_uint2(pack2(l0, l1), pack2(l2, l3));
}

// ---------------- Fused conversion kernel ----------------
__global__ __launch_bounds__(256) void conv_all(
    const float4* __restrict__ tok, const float4* __restrict__ W,
    const float*  __restrict__ A,   const float* __restrict__ Wg,
    const float4* __restrict__ B) {
    const int b = blockIdx.x;
    if (b < 16384) {
        size_t i = (size_t)b * 256 + threadIdx.x;
        split_store4(tok[i], (uint2*)g_Ah + i, (uint2*)g_Al + i);
    } else if (b < 17408) {
        size_t i = (size_t)(b - 16384) * 256 + threadIdx.x;
        split_store4(W[i], (uint2*)g_Wh + i, (uint2*)g_Wl + i);
    } else if (b < 18048) {
        int i = (b - 17408) * 256 + threadIdx.x;
        if (i < 160 * 1024) {
            int d = i / 160, j = i % 160;
            float v = 0.f;
            if (j < 128) { int e = j >> 4, r = j & 15; v = A[(size_t)e * 16384 + d * 16 + r]; }
            else if (j < 136) v = Wg[(size_t)d * 8 + (j - 128)];
            __nv_bfloat16 h, l; split2(v, h, l);
            g_Bc_h[i] = h; g_Bc_l[i] = l;
        }
    } else {
        size_t i = (size_t)(b - 18048) * 256 + threadIdx.x;
        split_store4(B[i], (uint2*)g_Bf_h + i, (uint2*)g_Bf_l + i);
    }
}

// ---------------- GEMM1 + fused router (BM=64) ----------
__global__ __launch_bounds__(256, 2) void gemm1_mma(float* __restrict__ out_logits,
                                                    float* __restrict__ out_sel,
                                                    float* __restrict__ out_wts) {
    constexpr int BM = 64, BN = 160, BK = 32, NST = 4;
    constexpr int HN = BN / 2, N8 = HN / 8, NT2 = N8 / 2;   // 80, 10, 5
    constexpr int LDA = BK + 8, LDB = BN + 8;
    constexpr uint32_t ASZ = BM * LDA * 2, BSZ = BK * LDB * 2;
    constexpr uint32_t STG = ASZ + BSZ;
    constexpr int LDH = 164;

    extern __shared__ __align__(16) char smem[];
    const uint32_t sA = s2u(smem);
    const uint32_t sB = sA + ASZ;
    float* hsm = (float*)smem;

    const int tid = threadIdx.x, w = tid >> 5, lane = tid & 31;
    const int wm = w & 3, wn = w >> 2;
    const int lr = lane & 15, lc8 = (lane >> 4) * 8;
    const int bm = blockIdx.y * BM;

    const __nv_bfloat16* Asrc[3] = { g_Ah, g_Ah, g_Al };
    const __nv_bfloat16* Bsrc[3] = { g_Bc_h, g_Bc_l, g_Bc_h };
    constexpr int TOT = 3072 / BK;   // 96

    auto load_tile = [&](int t, int buf) {
        int kg = t * BK;
        int si = kg >> 10;
        int ko = kg & 1023;
        const __nv_bfloat16* Ap = Asrc[si] + (size_t)bm * 1024 + ko;
        const __nv_bfloat16* Bp = Bsrc[si] + (size_t)ko * 160;
        const uint32_t dA = sA + buf * STG, dB = sB + buf * STG;
        {
            int row = tid >> 2, c = tid & 3;
            cp16(dA + (row * LDA + c * 8) * 2, Ap + (size_t)row * 1024 + c * 8);
        }
        #pragma unroll
        for (int i = 0; i < 3; i++) {
            int idx = tid + i * 256;
            if (idx < 640) {
                int row = idx / 20, c = idx % 20;
                cp16(dB + (row * LDB + c * 8) * 2, Bp + (size_t)row * 160 + c * 8);
            }
        }
    };

    float acc[N8][4];
    #pragma unroll
    for (int nt = 0; nt < N8; nt++)
        #pragma unroll
        for (int q = 0; q < 4; q++) acc[nt][q] = 0.f;

    const uint32_t aab = sA + ((wm * 16 + lr) * LDA + lc8) * 2;
    uint32_t bab[NT2];
    #pragma unroll
    for (int nt2 = 0; nt2 < NT2; nt2++)
        bab[nt2] = sB + (lr * LDB + wn * HN + nt2 * 16 + lc8) * 2;

    #pragma unroll
    for (int p = 0; p < NST - 1; p++) { load_tile(p, p); CP_COMMIT(); }

    for (int t = 0; t < TOT; t++) {
        const int buf = t & (NST - 1);
        asm volatile("cp.async.wait_group %0;" :: "n"(NST - 2));
        __syncthreads();
        if (t + NST - 1 < TOT) load_tile(t + NST - 1, (t + NST - 1) & (NST - 1));
        CP_COMMIT();

        const uint32_t off = buf * STG;
        #pragma unroll
        for (int kk = 0; kk < BK; kk += 16) {
            uint32_t af[4];
            ldsm4(af, aab + off + kk * 2);
            #pragma unroll
            for (int nt2 = 0; nt2 < NT2; nt2++) {
                uint32_t bf[4];
                ldsm4t(bf, bab[nt2] + off + kk * LDB * 2);
                mma_bf16(acc[2 * nt2],     af, bf[0], bf[1]);
                mma_bf16(acc[2 * nt2 + 1], af, bf[2], bf[3]);
            }
        }
    }

    asm volatile("cp.async.wait_group 0;" ::: "memory");
    __syncthreads();
    {
        int r0 = wm * 16 + (lane >> 2);
        #pragma unroll
        for (int nt = 0; nt < N8; nt++) {
            int c0 = wn * HN + nt * 8 + 2 * (lane & 3);
            hsm[r0 * LDH + c0]           = acc[nt][0];
            hsm[r0 * LDH + c0 + 1]       = acc[nt][1];
            hsm[(r0 + 8) * LDH + c0]     = acc[nt][2];
            hsm[(r0 + 8) * LDH + c0 + 1] = acc[nt][3];
        }
    }
    __syncthreads();

    {
        const int r = tid >> 2, q = tid & 3;
        const int n = bm + r;
        const float* hrow = hsm + r * LDH;
        float v0 = -1e30f; int i0 = 0;
        #pragma unroll
        for (int e = 0; e < 8; e++) {
            float v = hrow[128 + e];
            if (v > v0) { v0 = v; i0 = e; }
        }
        float v1 = -1e30f; int i1 = 0;
        #pragma unroll
        for (int e = 0; e < 8; e++) {
            float v = hrow[128 + e];
            if (e != i0 && v > v1) { v1 = v; i1 = e; }
        }
        float e1v = __expf(v1 - v0);
        float p0 = 1.0f / (1.0f + e1v);
        float p1 = e1v * p0;
        if (q == 0) {
            #pragma unroll
            for (int e = 0; e < 8; e++)
                out_logits[(size_t)n * 8 + e] = hrow[128 + e];
            out_sel[(size_t)n * 2 + 0] = (float)i0;
            out_sel[(size_t)n * 2 + 1] = (float)i1;
            out_wts[(size_t)n * 2 + 0] = p0;
            out_wts[(size_t)n * 2 + 1] = p1;
        }
        const float s0 = SCALING * p0, s1 = SCALING * p1;
        const int jbase = q * 32;
        #pragma unroll
        for (int j4 = 0; j4 < 32; j4 += 4) {
            int j = jbase + j4;
            int e = j >> 4;
            float g = (e == i0) ? s0 : ((e == i1) ? s1 : 0.f);
            float4 h4 = *(const float4*)(hrow + j);
            __nv_bfloat16 h0, h1, h2, h3, l0, l1, l2, l3;
            split2(h4.x * g, h0, l0); split2(h4.y * g, h1, l1);
            split2(h4.z * g, h2, l2); split2(h4.w * g, h3, l3);
            *(uint2*)&g_Hh[(size_t)n * 128 + j] = make_uint2(pack2(h0, h1), pack2(h2, h3));
            *(uint2*)&g_Hl[(size_t)n * 128 + j] = make_uint2(pack2(l0, l1), pack2(l2, l3));
        }
    }
}

// ---------------- GEMM2: merged 3-pass split-bf16, BK=32 chunks ----------
// out = tokens @ W (3-pass: AhWh + AhWl + AlWh, merged per k-chunk)
//     + H @ Bf    (1-pass hi-only tail, K=128)
// BM=128, BN=128, 128 thr (2m x 2n warps, 64x64 warp tile), NST=3.
// Stage holds Ah|Al|Wh|Wl (37,888 B); one barrier serves 3 MMA passes.
__global__ __launch_bounds__(128, 2) void gemm2_mma(float* __restrict__ outp) {
    constexpr int BM = 128, BN = 128, BK = 32, NST = 3;
    constexpr int LDA = BK + 8, LDB = BN + 8;
    constexpr uint32_t AT = BM * LDA * 2;        // 10240 per A tile
    constexpr uint32_t BT = BK * LDB * 2;        // 8704 per B tile
    constexpr uint32_t STG = 2 * AT + 2 * BT;    // 37888
    constexpr int TOT_MAIN = 1024 / BK;          // 32
    constexpr int TOT = TOT_MAIN + 128 / BK;     // 36

    extern __shared__ __align__(16) char smem[];
    const uint32_t sAh = s2u(smem);
    const uint32_t sAl = sAh + AT;
    const uint32_t sWh = sAh + 2 * AT;
    const uint32_t sWl = sWh + BT;

    const int tid = threadIdx.x, w = tid >> 5, lane = tid & 31;
    const int wm = w & 1, wn = w >> 1;
    const int lr = lane & 15, lc8 = (lane >> 4) * 8;
    const int bm = blockIdx.y * BM;
    const int bn = blockIdx.x * BN;

    auto load_tile = [&](int t, int buf) {
        const uint32_t so = buf * STG;
        if (t < TOT_MAIN) {
            int ko = t * BK;
            const __nv_bfloat16* Ah = g_Ah + (size_t)bm * 1024 + ko;
            const __nv_bfloat16* Al = g_Al + (size_t)bm * 1024 + ko;
            const __nv_bfloat16* Wh = g_Wh + (size_t)ko * 1024 + bn;
            const __nv_bfloat16* Wl = g_Wl + (size_t)ko * 1024 + bn;
            #pragma unroll
            for (int i = 0; i < 4; i++) {             // A tiles: 512 cp16 each
                int idx = tid + i * 128;
                int row = idx >> 2, c = idx & 3;
                uint32_t d = (row * LDA + c * 8) * 2;
                size_t  g = (size_t)row * 1024 + c * 8;
                cp16(sAh + so + d, Ah + g);
                cp16(sAl + so + d, Al + g);
            }
            #pragma unroll
            for (int i = 0; i < 4; i++) {             // B tiles: 512 cp16 each
                int idx = tid + i * 128;
                int row = idx >> 4, c = idx & 15;
                uint32_t d = (row * LDB + c * 8) * 2;
                size_t  g = (size_t)row * 1024 + c * 8;
                cp16(sWh + so + d, Wh + g);
                cp16(sWl + so + d, Wl + g);
            }
        } else {                                      // LoRA tail: hi tiles only
            int ko = (t - TOT_MAIN) * BK;
            const __nv_bfloat16* Ah = g_Hh + (size_t)bm * 128 + ko;
            const __nv_bfloat16* Wh = g_Bf_h + (size_t)ko * 1024 + bn;
            #pragma unroll
            for (int i = 0; i < 4; i++) {
                int idx = tid + i * 128;
                int row = idx >> 2, c = idx & 3;
                cp16(sAh + so + (row * LDA + c * 8) * 2,
                     Ah + (size_t)row * 128 + c * 8);
            }
            #pragma unroll
            for (int i = 0; i < 4; i++) {
                int idx = tid + i * 128;
                int row = idx >> 4, c = idx & 15;
                cp16(sWh + so + (row * LDB + c * 8) * 2,
                     Wh + (size_t)row * 1024 + c * 8);
            }
        }
    };

    float acc[4][8][4];
    #pragma unroll
    for (int mt = 0; mt < 4; mt++)
        #pragma unroll
        for (int nt = 0; nt < 8; nt++)
            #pragma unroll
            for (int q = 0; q < 4; q++) acc[mt][nt][q] = 0.f;

    uint32_t aab[4], bab[4];
    #pragma unroll
    for (int mt = 0; mt < 4; mt++)
        aab[mt] = sAh + ((wm * 64 + mt * 16 + lr) * LDA + lc8) * 2;
    #pragma unroll
    for (int nt2 = 0; nt2 < 4; nt2++)
        bab[nt2] = sWh + (lr * LDB + wn * 64 + nt2 * 16 + lc8) * 2;

    #pragma unroll
    for (int p = 0; p < NST - 1; p++) { load_tile(p, p); CP_COMMIT(); }

    int buf = 0, pbuf = NST - 1;
    for (int t = 0; t < TOT; t++) {
        asm volatile("cp.async.wait_group %0;" :: "n"(NST - 2));
        __syncthreads();
        if (t + NST - 1 < TOT) load_tile(t + NST - 1, pbuf);
        CP_COMMIT();
        if (++pbuf == NST) pbuf = 0;

        const uint32_t off = buf * STG;
        if (++buf == NST) buf = 0;

        if (t < TOT_MAIN) {
            #pragma unroll
            for (int kk = 0; kk < BK; kk += 16) {
                uint32_t ah[4][4], al[4][4];
                #pragma unroll
                for (int mt = 0; mt < 4; mt++) {
                    ldsm4(ah[mt], aab[mt] + off + kk * 2);
                    ldsm4(al[mt], aab[mt] + off + kk * 2 + AT);
                }
                #pragma unroll
                for (int nt2 = 0; nt2 < 4; nt2++) {
                    uint32_t bh[4], bl[4];
                    ldsm4t(bh, bab[nt2] + off + kk * LDB * 2);
                    ldsm4t(bl, bab[nt2] + off + kk * LDB * 2 + BT);
                    #pragma unroll
                    for (int mt = 0; mt < 4; mt++) {
                        mma_bf16(acc[mt][2 * nt2],     ah[mt], bh[0], bh[1]);
                        mma_bf16(acc[mt][2 * nt2 + 1], ah[mt], bh[2], bh[3]);
                        mma_bf16(acc[mt][2 * nt2],     ah[mt], bl[0], bl[1]);
                        mma_bf16(acc[mt][2 * nt2 + 1], ah[mt], bl[2], bl[3]);
                        mma_bf16(acc[mt][2 * nt2],     al[mt], bh[0], bh[1]);
                        mma_bf16(acc[mt][2 * nt2 + 1], al[mt], bh[2], bh[3]);
                    }
                }
            }
        } else {
            #pragma unroll
            for (int kk = 0; kk < BK; kk += 16) {
                uint32_t ah[4][4];
                #pragma unroll
                for (int mt = 0; mt < 4; mt++)
                    ldsm4(ah[mt], aab[mt] + off + kk * 2);
                #pragma unroll
                for (int nt2 = 0; nt2 < 4; nt2++) {
                    uint32_t bh[4];
                    ldsm4t(bh, bab[nt2] + off + kk * LDB * 2);
                    #pragma unroll
                    for (int mt = 0; mt < 4; mt++) {
                        mma_bf16(acc[mt][2 * nt2],     ah[mt], bh[0], bh[1]);
                        mma_bf16(acc[mt][2 * nt2 + 1], ah[mt], bh[2], bh[3]);
                    }
                }
            }
        }
    }

    #pragma unroll
    for (int mt = 0; mt < 4; mt++) {
        int r0 = bm + wm * 64 + mt * 16 + (lane >> 2);
        #pragma unroll
        for (int nt = 0; nt < 8; nt++) {
            int c0 = bn + wn * 64 + nt * 8 + 2 * (lane & 3);
            *(float2*)(outp + (size_t)r0 * D_OUT + c0) =
                make_float2(acc[mt][nt][0], acc[mt][nt][1]);
            *(float2*)(outp + (size_t)(r0 + 8) * D_OUT + c0) =
                make_float2(acc[mt][nt][2], acc[mt][nt][3]);
        }
    }
}

// ---------------- Launch ----------------
extern "C" void kernel_launch(void* const* d_in, const int* in_sizes, int n_in,
                              void* d_out, int out_size) {
    const float* tokens = (const float*)d_in[0];
    const float* W_base = (const float*)d_in[1];
    const float* A      = (const float*)d_in[2];
    const float* B      = (const float*)d_in[3];
    const float* W_gate = (const float*)d_in[4];

    float* out        = (float*)d_out;
    float* out_logits = out + (size_t)N_TOK * D_OUT;
    float* out_sel    = out_logits + (size_t)N_TOK * N_EXP;
    float* out_wts    = out_sel + (size_t)N_TOK * 2;

    const int smem1 = 4 * (64 * 40 + 32 * 168) * 2;        // 63,488 B
    const int smem2 = 3 * (2 * 128 * 40 + 2 * 32 * 136) * 2;  // 113,664 B

    cudaFuncSetAttribute(gemm1_mma,
                         cudaFuncAttributeMaxDynamicSharedMemorySize, smem1);
    cudaFuncSetAttribute(gemm2_mma,
                         cudaFuncAttributeMaxDynamicSharedMemorySize, smem2);

    conv_all<<<18176, 256>>>((const float4*)tokens, (const float4*)W_base,
                             A, W_gate, (const float4*)B);

    gemm1_mma<<<dim3(1, N_TOK / 64), 256, smem1>>>(out_logits, out_sel, out_wts);

    gemm2_mma<<<dim3(D_OUT / 128, N_TOK / 128), 128, smem2>>>(out);
}